// round 10
// baseline (speedup 1.0000x reference)
#include <cuda_runtime.h>
#include <cstdint>

// Sparse transposed conv: gather-GEMM-scatter over rulebook.
// x:[N_SRC,32] f32, weight:[K,32,16] f32, src/dst:[K,M] i32, out:[N_TGT,16] f32.
// v9 = v6 inner kernel (184us winner) + cross-tile double-buffered pipeline:
//   each block runs 4 tiles of 256 pairs; staging of tile t+1 is in flight
//   while tile t computes (wait_group 1). Weight loaded once per block.

#define CIN   32
#define COUT  16
#define TPB   256
#define PPB   256                 // pairs per tile
#define TILES 4                   // tiles per block
#define NITER ((PPB * 8) / TPB)   // 8 cp.async (16B) per thread per tile

typedef unsigned long long ull;
typedef unsigned int       u32;

#define FMA2(acc, a, b) \
    asm("fma.rn.f32x2 %0, %1, %2, %0;" : "+l"(acc) : "l"(a), "l"(b))

#define UNPACK2(lo, hi, v) \
    asm("mov.b64 {%0, %1}, %2;" : "=f"(lo), "=f"(hi) : "l"(v))

// dynamic smem: [0,2048) wsm ; [2048,+32K) buf0 ; [+32K,+64K) buf1
#define XSM_OFF   2048
#define BUF_BYTES (PPB * 8 * 16)              // 32768
#define SMEM_BYTES (XSM_OFF + 2 * BUF_BYTES)  // 67584

__global__ __launch_bounds__(TPB, 3)
void rulebook_gemm_scatter(const float* __restrict__ x,
                           const float* __restrict__ w,
                           const int*   __restrict__ src_idx,
                           const int*   __restrict__ dst_idx,
                           float*       __restrict__ out,
                           int M)
{
    extern __shared__ char smem[];
    float* wsm = (float*)smem;

    const int k     = blockIdx.y;
    const int base0 = blockIdx.x * (PPB * TILES);
    const long long kbase = (long long)k * M;

    u32 xsm_base;
    asm("{ .reg .u64 t; cvta.to.shared.u64 t, %1; cvt.u32.u64 %0, t; }"
        : "=r"(xsm_base) : "l"(smem + XSM_OFF));

    // ---- weight[k] -> smem once, interleaved: word = cp*32 + j*2 + (c&1) ----
    const float* wk = w + (size_t)k * (CIN * COUT);
    #pragma unroll
    for (int i = 0; i < (CIN * COUT) / TPB; i++) {
        int t = i * TPB + threadIdx.x;
        int c = t >> 4, j = t & 15;
        wsm[(c >> 1) * 32 + j * 2 + (c & 1)] = __ldg(wk + t);
    }

    const int g  = threadIdx.x >> 2;     // group: owns pairs g*4..g*4+3
    const int l  = threadIdx.x & 3;      // lane: owns couts 4l..4l+3
    const int sw = g & 7;
    const longlong2* wsm2 = (const longlong2*)wsm;

    // ---- staging helper (tile t -> buffer t&1), 8-lane full-row cp.async ----
    auto stage = [&](int t) {
        const int pt = base0 + t * PPB;
        const int np = min(PPB, M - pt);          // may be <=0
        if (np > 0) {
            const long long kb = kbase + pt;
            const u32 bufb = xsm_base + (u32)(t & 1) * BUF_BYTES;
            #pragma unroll
            for (int i = 0; i < NITER; i++) {
                int idx = i * TPB + threadIdx.x;
                int r = idx >> 3, j = idx & 7;
                int rc = (r < np) ? r : 0;
                int s = __ldg(src_idx + kb + rc);
                const float4* src = reinterpret_cast<const float4*>(x) + (size_t)s * 8 + j;
                u32 dst = bufb + (u32)(r * 8 + (j ^ ((r >> 2) & 7))) * 16;
                asm volatile("cp.async.cg.shared.global [%0], [%1], 16;"
                             :: "r"(dst), "l"(src));
            }
        }
        asm volatile("cp.async.commit_group;");
    };

    // prologue: tiles 0 and 1 in flight
    stage(0);
    stage(1);

    #pragma unroll
    for (int t = 0; t < TILES; t++) {
        const int pt = base0 + t * PPB;
        const int np = min(PPB, M - pt);
        const long long kb = kbase + pt;
        const float4* xsm = (const float4*)(smem + XSM_OFF + (t & 1) * BUF_BYTES);

        // dst indices for this tile (L2-resident, overlap with wait)
        int dsts[4];
        #pragma unroll
        for (int ii = 0; ii < 4; ii++) {
            int r = g * 4 + ii;
            dsts[ii] = (r < np) ? __ldg(dst_idx + kb + r) : -1;
        }

        if (t + 2 < TILES) asm volatile("cp.async.wait_group 1;");
        else               asm volatile("cp.async.wait_group 0;");
        __syncthreads();

        if (np > 0) {
            ull acc[4][4];
            #pragma unroll
            for (int ii = 0; ii < 4; ii++)
                #pragma unroll
                for (int m = 0; m < 4; m++) acc[ii][m] = 0ull;

            #pragma unroll
            for (int jj = 0; jj < 8; jj++) {
                const longlong2 wa0 = wsm2[(2 * jj) * 8 + 2 * l];
                const longlong2 wa1 = wsm2[(2 * jj) * 8 + 2 * l + 1];
                const longlong2 wb0 = wsm2[(2 * jj + 1) * 8 + 2 * l];
                const longlong2 wb1 = wsm2[(2 * jj + 1) * 8 + 2 * l + 1];
                #pragma unroll
                for (int ii = 0; ii < 4; ii++) {
                    const int r = g * 4 + ii;
                    longlong2 xv = *(const longlong2*)&xsm[r * 8 + (jj ^ sw)];
                    const ull xlo = (ull)xv.x;   // channels 4jj, 4jj+1
                    const ull xhi = (ull)xv.y;   // channels 4jj+2, 4jj+3
                    FMA2(acc[ii][0], xlo, (ull)wa0.x);
                    FMA2(acc[ii][1], xlo, (ull)wa0.y);
                    FMA2(acc[ii][2], xlo, (ull)wa1.x);
                    FMA2(acc[ii][3], xlo, (ull)wa1.y);
                    FMA2(acc[ii][0], xhi, (ull)wb0.x);
                    FMA2(acc[ii][1], xhi, (ull)wb0.y);
                    FMA2(acc[ii][2], xhi, (ull)wb1.x);
                    FMA2(acc[ii][3], xhi, (ull)wb1.y);
                }
            }

            // scatter direct from regs: each warp red.v4 = 8 pairs / 8 lines
            #pragma unroll
            for (int ii = 0; ii < 4; ii++) {
                if (dsts[ii] < 0) continue;
                float l0, h0, l1, h1, l2, h2, l3, h3;
                UNPACK2(l0, h0, acc[ii][0]);
                UNPACK2(l1, h1, acc[ii][1]);
                UNPACK2(l2, h2, acc[ii][2]);
                UNPACK2(l3, h3, acc[ii][3]);
                float* o = out + (size_t)dsts[ii] * COUT + 4 * l;
                asm volatile("red.global.add.v4.f32 [%0], {%1, %2, %3, %4};"
                             :: "l"(o),
                                "f"(l0 + h0), "f"(l1 + h1),
                                "f"(l2 + h2), "f"(l3 + h3) : "memory");
            }
        }

        __syncthreads();                 // all reads of buf[t&1] done
        if (t + 2 < TILES) stage(t + 2); // overwrite buf[t&1] for tile t+2
    }
}

extern "C" void kernel_launch(void* const* d_in, const int* in_sizes, int n_in,
                              void* d_out, int out_size)
{
    const float* x       = (const float*)d_in[0];
    const float* weight  = (const float*)d_in[1];
    const int*   src_idx = (const int*)d_in[2];
    const int*   dst_idx = (const int*)d_in[3];
    float*       out     = (float*)d_out;

    const int K = in_sizes[1] / (CIN * COUT);   // 27
    const int M = in_sizes[2] / K;              // 200000

    cudaMemsetAsync(d_out, 0, (size_t)out_size * sizeof(float), 0);

    cudaFuncSetAttribute(rulebook_gemm_scatter,
                         cudaFuncAttributeMaxDynamicSharedMemorySize, SMEM_BYTES);

    const int span = PPB * TILES;               // 1024 pairs per block
    dim3 grid((M + span - 1) / span, K);
    rulebook_gemm_scatter<<<grid, TPB, SMEM_BYTES>>>(x, weight, src_idx, dst_idx, out, M);
}

// round 12
// speedup vs baseline: 1.0219x; 1.0219x over previous
#include <cuda_runtime.h>
#include <cstdint>

// Sparse transposed conv: gather-GEMM-scatter over rulebook.
// x:[N_SRC,32] f32, weight:[K,32,16] f32, src/dst:[K,M] i32, out:[N_TGT,16] f32.
// v11: one-wave persistent blocks. TPB=128, PPB=128, 6 blocks/SM (34KB smem).
//      Each block owns k=blockIdx.y and tiles blockIdx.x, +NBX, ... with
//      double-buffered cp.async staging (stage t+1 while computing t).
//      Inner tile = v6 winner: 4-lane-per-pair ownership, f32x2 FMA,
//      register-direct red.global.add.v4.f32 scatter.

#define CIN   32
#define COUT  16
#define TPB   128
#define PPB   128                 // pairs per tile
#define NBX   32                  // blocks per k  -> grid 32*27=864 (1 wave @6/SM)
#define NITER ((PPB * 8) / TPB)   // 8 cp.async (16B) per thread per tile

typedef unsigned long long ull;
typedef unsigned int       u32;

#define FMA2(acc, a, b) \
    asm("fma.rn.f32x2 %0, %1, %2, %0;" : "+l"(acc) : "l"(a), "l"(b))

#define UNPACK2(lo, hi, v) \
    asm("mov.b64 {%0, %1}, %2;" : "=f"(lo), "=f"(hi) : "l"(v))

// dynamic smem: [0,2048) wsm (f32x2-interleaved) ; two 16KB x buffers
#define XSM_OFF   2048
#define BUF_BYTES (PPB * 8 * 16)               // 16384
#define SMEM_BYTES (XSM_OFF + 2 * BUF_BYTES)   // 34816

__global__ __launch_bounds__(TPB, 6)
void rulebook_gemm_scatter(const float* __restrict__ x,
                           const float* __restrict__ w,
                           const int*   __restrict__ src_idx,
                           const int*   __restrict__ dst_idx,
                           float*       __restrict__ out,
                           int M)
{
    extern __shared__ char smem[];
    float* wsm = (float*)smem;

    const int k = blockIdx.y;
    const long long kbase = (long long)k * M;
    const int ntiles = (M + PPB - 1) / PPB;

    u32 xsm_base;
    asm("{ .reg .u64 t; cvta.to.shared.u64 t, %1; cvt.u32.u64 %0, t; }"
        : "=r"(xsm_base) : "l"(smem + XSM_OFF));

    // ---- weight[k] -> smem once, interleaved: word = cp*32 + j*2 + (c&1) ----
    const float* wk = w + (size_t)k * (CIN * COUT);
    #pragma unroll
    for (int i = 0; i < (CIN * COUT) / TPB; i++) {
        int t = i * TPB + threadIdx.x;
        int c = t >> 4, j = t & 15;
        wsm[(c >> 1) * 32 + j * 2 + (c & 1)] = __ldg(wk + t);
    }

    const int g  = threadIdx.x >> 2;     // 32 groups; group owns pairs g*4..g*4+3
    const int l  = threadIdx.x & 3;      // lane owns couts 4l..4l+3
    const int sw = g & 7;
    const longlong2* wsm2 = (const longlong2*)wsm;

    // staging: tile -> buffer b (8 lanes x 16B per row, full-line coalesced)
    auto stage = [&](int tile, int b) {
        const int pt = tile * PPB;
        const int np = min(PPB, M - pt);
        const long long kb = kbase + pt;
        const u32 bufb = xsm_base + (u32)b * BUF_BYTES;
        #pragma unroll
        for (int i = 0; i < NITER; i++) {
            int idx = i * TPB + threadIdx.x;
            int r = idx >> 3, j = idx & 7;
            int rc = (r < np) ? r : 0;
            int s = __ldg(src_idx + kb + rc);
            const float4* src = reinterpret_cast<const float4*>(x) + (size_t)s * 8 + j;
            u32 dst = bufb + (u32)(r * 8 + (j ^ ((r >> 2) & 7))) * 16;
            asm volatile("cp.async.cg.shared.global [%0], [%1], 16;"
                         :: "r"(dst), "l"(src));
        }
    };

    int tile = blockIdx.x;
    if (tile < ntiles) stage(tile, 0);
    asm volatile("cp.async.commit_group;");

    int buf = 0;
    for (; tile < ntiles; tile += NBX, buf ^= 1) {
        const int nxt = tile + NBX;
        if (nxt < ntiles) stage(nxt, buf ^ 1);
        asm volatile("cp.async.commit_group;");      // always: keeps group count aligned

        const int pt = tile * PPB;
        const int np = min(PPB, M - pt);
        const long long kb = kbase + pt;

        // scatter indices (overlap with the wait)
        int dsts[4];
        #pragma unroll
        for (int ii = 0; ii < 4; ii++) {
            int r = g * 4 + ii;
            dsts[ii] = (r < np) ? __ldg(dst_idx + kb + r) : -1;
        }

        asm volatile("cp.async.wait_group 1;");      // current tile's group done
        __syncthreads();

        const float4* xsm = (const float4*)(smem + XSM_OFF + buf * BUF_BYTES);

        ull acc[4][4];
        #pragma unroll
        for (int ii = 0; ii < 4; ii++)
            #pragma unroll
            for (int m = 0; m < 4; m++) acc[ii][m] = 0ull;

        #pragma unroll
        for (int jj = 0; jj < 8; jj++) {
            const longlong2 wa0 = wsm2[(2 * jj) * 8 + 2 * l];
            const longlong2 wa1 = wsm2[(2 * jj) * 8 + 2 * l + 1];
            const longlong2 wb0 = wsm2[(2 * jj + 1) * 8 + 2 * l];
            const longlong2 wb1 = wsm2[(2 * jj + 1) * 8 + 2 * l + 1];
            #pragma unroll
            for (int ii = 0; ii < 4; ii++) {
                const int r = g * 4 + ii;
                longlong2 xv = *(const longlong2*)&xsm[r * 8 + (jj ^ sw)];
                const ull xlo = (ull)xv.x;   // channels 4jj, 4jj+1
                const ull xhi = (ull)xv.y;   // channels 4jj+2, 4jj+3
                FMA2(acc[ii][0], xlo, (ull)wa0.x);
                FMA2(acc[ii][1], xlo, (ull)wa0.y);
                FMA2(acc[ii][2], xlo, (ull)wa1.x);
                FMA2(acc[ii][3], xlo, (ull)wa1.y);
                FMA2(acc[ii][0], xhi, (ull)wb0.x);
                FMA2(acc[ii][1], xhi, (ull)wb0.y);
                FMA2(acc[ii][2], xhi, (ull)wb1.x);
                FMA2(acc[ii][3], xhi, (ull)wb1.y);
            }
        }

        __syncthreads();   // all reads of buf done; next iter may overwrite it

        // scatter direct from regs: each warp red.v4 = 8 pairs / 8 lines
        #pragma unroll
        for (int ii = 0; ii < 4; ii++) {
            if (dsts[ii] < 0) continue;
            float l0, h0, l1, h1, l2, h2, l3, h3;
            UNPACK2(l0, h0, acc[ii][0]);
            UNPACK2(l1, h1, acc[ii][1]);
            UNPACK2(l2, h2, acc[ii][2]);
            UNPACK2(l3, h3, acc[ii][3]);
            float* o = out + (size_t)dsts[ii] * COUT + 4 * l;
            asm volatile("red.global.add.v4.f32 [%0], {%1, %2, %3, %4};"
                         :: "l"(o),
                            "f"(l0 + h0), "f"(l1 + h1),
                            "f"(l2 + h2), "f"(l3 + h3) : "memory");
        }
    }
}

extern "C" void kernel_launch(void* const* d_in, const int* in_sizes, int n_in,
                              void* d_out, int out_size)
{
    const float* x       = (const float*)d_in[0];
    const float* weight  = (const float*)d_in[1];
    const int*   src_idx = (const int*)d_in[2];
    const int*   dst_idx = (const int*)d_in[3];
    float*       out     = (float*)d_out;

    const int K = in_sizes[1] / (CIN * COUT);   // 27
    const int M = in_sizes[2] / K;              // 200000

    cudaMemsetAsync(d_out, 0, (size_t)out_size * sizeof(float), 0);

    cudaFuncSetAttribute(rulebook_gemm_scatter,
                         cudaFuncAttributeMaxDynamicSharedMemorySize, SMEM_BYTES);

    dim3 grid(NBX, K);
    rulebook_gemm_scatter<<<grid, TPB, SMEM_BYTES>>>(x, weight, src_idx, dst_idx, out, M);
}

// round 13
// speedup vs baseline: 1.0331x; 1.0110x over previous
#include <cuda_runtime.h>
#include <cstdint>

// Sparse transposed conv: gather-GEMM-scatter over rulebook.
// x:[N_SRC,32] f32, weight:[K,32,16] f32, src/dst:[K,M] i32, out:[N_TGT,16] f32.
// v12: gather via cp.async.bulk (TMA path, 1 op = 1 full 128B row, mbarrier
//      expect_tx completion) -> staging leaves the LSU. Rows padded to 144B
//      and stride-64 group ownership => conflict-free LDS without swizzle.
//      Core unchanged from v6: 4-lane-per-pair, f32x2 FMA, red.v4 scatter.

#define CIN   32
#define COUT  16
#define TPB   256
#define PPB   256
#define ROWB  144                 // 128B row + 16B pad (bank skew)

typedef unsigned long long ull;
typedef unsigned int       u32;

#define FMA2(acc, a, b) \
    asm("fma.rn.f32x2 %0, %1, %2, %0;" : "+l"(acc) : "l"(a), "l"(b))

#define UNPACK2(lo, hi, v) \
    asm("mov.b64 {%0, %1}, %2;" : "=f"(lo), "=f"(hi) : "l"(v))

// dynamic smem: [0,2048) wsm ; [2048,2056) mbar ; [2176, 2176+256*144) xsm
#define MBAR_OFF 2048
#define XSM_OFF  2176
#define SMEM_BYTES (XSM_OFF + PPB * ROWB)     // 39040

__global__ __launch_bounds__(TPB, 4)
void rulebook_gemm_scatter(const float* __restrict__ x,
                           const float* __restrict__ w,
                           const int*   __restrict__ src_idx,
                           const int*   __restrict__ dst_idx,
                           float*       __restrict__ out,
                           int M)
{
    extern __shared__ char smem[];
    float* wsm = (float*)smem;
    const char* xbase = smem + XSM_OFF;

    const int k  = blockIdx.y;
    const int pb = blockIdx.x * PPB;
    const int npair = min(PPB, M - pb);
    const long long kb = (long long)k * M + pb;

    u32 smem_b;
    asm("{ .reg .u64 t; cvta.to.shared.u64 t, %1; cvt.u32.u64 %0, t; }"
        : "=r"(smem_b) : "l"(smem));
    const u32 mbar  = smem_b + MBAR_OFF;
    const u32 xsm_b = smem_b + XSM_OFF;

    const int tid = threadIdx.x;

    // ---- mbarrier init, then arm with full tile byte count ----
    if (tid == 0) {
        asm volatile("mbarrier.init.shared.b64 [%0], 1;" :: "r"(mbar) : "memory");
    }
    __syncthreads();
    if (tid == 0) {
        asm volatile("mbarrier.arrive.expect_tx.shared.b64 _, [%0], %1;"
                     :: "r"(mbar), "r"((u32)(PPB * 128)) : "memory");
    }

    // ---- gather: one 128B bulk copy per row, via TMA path ----
    {
        int rc = (tid < npair) ? tid : 0;
        int s = __ldg(src_idx + kb + rc);
        const float* src = x + (size_t)s * CIN;
        u32 dst = xsm_b + (u32)tid * ROWB;
        asm volatile(
            "cp.async.bulk.shared::cta.global.mbarrier::complete_tx::bytes "
            "[%0], [%1], 128, [%2];"
            :: "r"(dst), "l"(src), "r"(mbar) : "memory");
    }

    // ---- weight[k] -> smem, interleaved: word = cp*32 + j*2 + (c&1) ----
    const float* wk = w + (size_t)k * (CIN * COUT);
    #pragma unroll
    for (int i = 0; i < (CIN * COUT) / TPB; i++) {
        int t = i * TPB + tid;
        int c = t >> 4, j = t & 15;
        wsm[(c >> 1) * 32 + j * 2 + (c & 1)] = __ldg(wk + t);
    }

    // stride-64 ownership: group g owns pairs g, g+64, g+128, g+192;
    // lane l owns couts 4l..4l+3.
    const int g = tid >> 2;
    const int l = tid & 3;

    int dsts[4];
    #pragma unroll
    for (int ii = 0; ii < 4; ii++) {
        int r = g + 64 * ii;
        dsts[ii] = (r < npair) ? __ldg(dst_idx + kb + r) : -1;
    }

    // ---- wait for all bulk copies (acquire orders the smem reads) ----
    {
        u32 done;
        asm volatile(
            "{\n\t"
            ".reg .pred p;\n\t"
            "mbarrier.try_wait.parity.acquire.cta.shared::cta.b64 p, [%1], 0;\n\t"
            "selp.b32 %0, 1, 0, p;\n\t"
            "}"
            : "=r"(done) : "r"(mbar) : "memory");
        if (!done) {
            asm volatile(
                "{\n\t"
                ".reg .pred P;\n\t"
                "WAIT_%=:\n\t"
                "mbarrier.try_wait.parity.acquire.cta.shared::cta.b64 P, [%0], 0, 0x989680;\n\t"
                "@P bra.uni DONE_%=;\n\t"
                "bra.uni WAIT_%=;\n\t"
                "DONE_%=:\n\t"
                "}"
                :: "r"(mbar) : "memory");
        }
    }
    __syncthreads();   // also orders wsm writes

    // ---- compute: acc[ii][m] (f32x2 even-c/odd-c halves), m = cout-4l ----
    ull acc[4][4];
    #pragma unroll
    for (int ii = 0; ii < 4; ii++)
        #pragma unroll
        for (int m = 0; m < 4; m++) acc[ii][m] = 0ull;

    const longlong2* wsm2 = (const longlong2*)wsm;

    #pragma unroll
    for (int jj = 0; jj < 8; jj++) {
        const longlong2 wa0 = wsm2[(2 * jj) * 8 + 2 * l];
        const longlong2 wa1 = wsm2[(2 * jj) * 8 + 2 * l + 1];
        const longlong2 wb0 = wsm2[(2 * jj + 1) * 8 + 2 * l];
        const longlong2 wb1 = wsm2[(2 * jj + 1) * 8 + 2 * l + 1];
        #pragma unroll
        for (int ii = 0; ii < 4; ii++) {
            const int r = g + 64 * ii;
            // bank16 = (9r + jj) mod 8 = (r + jj) mod 8: 8 consecutive rows
            // per warp -> 8 distinct banks; 4 lanes/group broadcast.
            longlong2 xv = *(const longlong2*)(xbase + r * ROWB + jj * 16);
            const ull xlo = (ull)xv.x;   // channels 4jj, 4jj+1
            const ull xhi = (ull)xv.y;   // channels 4jj+2, 4jj+3
            FMA2(acc[ii][0], xlo, (ull)wa0.x);
            FMA2(acc[ii][1], xlo, (ull)wa0.y);
            FMA2(acc[ii][2], xlo, (ull)wa1.x);
            FMA2(acc[ii][3], xlo, (ull)wa1.y);
            FMA2(acc[ii][0], xhi, (ull)wb0.x);
            FMA2(acc[ii][1], xhi, (ull)wb0.y);
            FMA2(acc[ii][2], xhi, (ull)wb1.x);
            FMA2(acc[ii][3], xhi, (ull)wb1.y);
        }
    }

    // ---- scatter direct from regs: each warp red.v4 = 8 pairs / 8 lines ----
    #pragma unroll
    for (int ii = 0; ii < 4; ii++) {
        if (dsts[ii] < 0) continue;
        float l0, h0, l1, h1, l2, h2, l3, h3;
        UNPACK2(l0, h0, acc[ii][0]);
        UNPACK2(l1, h1, acc[ii][1]);
        UNPACK2(l2, h2, acc[ii][2]);
        UNPACK2(l3, h3, acc[ii][3]);
        float* o = out + (size_t)dsts[ii] * COUT + 4 * l;
        asm volatile("red.global.add.v4.f32 [%0], {%1, %2, %3, %4};"
                     :: "l"(o),
                        "f"(l0 + h0), "f"(l1 + h1),
                        "f"(l2 + h2), "f"(l3 + h3) : "memory");
    }
}

extern "C" void kernel_launch(void* const* d_in, const int* in_sizes, int n_in,
                              void* d_out, int out_size)
{
    const float* x       = (const float*)d_in[0];
    const float* weight  = (const float*)d_in[1];
    const int*   src_idx = (const int*)d_in[2];
    const int*   dst_idx = (const int*)d_in[3];
    float*       out     = (float*)d_out;

    const int K = in_sizes[1] / (CIN * COUT);   // 27
    const int M = in_sizes[2] / K;              // 200000

    cudaMemsetAsync(d_out, 0, (size_t)out_size * sizeof(float), 0);

    cudaFuncSetAttribute(rulebook_gemm_scatter,
                         cudaFuncAttributeMaxDynamicSharedMemorySize, SMEM_BYTES);

    dim3 grid((M + PPB - 1) / PPB, K);
    rulebook_gemm_scatter<<<grid, TPB, SMEM_BYTES>>>(x, weight, src_idx, dst_idx, out, M);
}